// round 14
// baseline (speedup 1.0000x reference)
#include <cuda_runtime.h>
#include <cuda_bf16.h>

#define NQ 8
#define FULLMASK 0xffffffffu

// One sample per 4 lanes; lane l owns rows e0=2l, e1=2l+1.
// Every lane redundantly loads the whole sample's q,v (L1-broadcast) so all
// trig/cumsum work is local; shuffles remain only in GE pivot broadcasts.
__global__ void __launch_bounds__(128, 7) acrobot_dyn_kernel(
    const float* __restrict__ q_in, const float* __restrict__ v_in,
    const float* __restrict__ u_in, const float* __restrict__ p,
    float* __restrict__ out, int Btot /* = B*NQ */)
{
    // ---- uniform coefficient tables (once per CTA) ----
    __shared__ float2 sCo[NQ][NQ + 1];  // (A, IsOrD); diag = (0, D[i])
    __shared__ float sGc[NQ];           // g * ls_k * (ms_suf_k - 0.5*ms_k)
    __shared__ float sTau[NQ];

    if (threadIdx.x == 0) {
        float ms[NQ], ls[NQ], ms_suf[NQ], Is_suf[NQ];
#pragma unroll
        for (int i = 0; i < NQ; i++) {
            ms[i] = p[i];
            ls[i] = p[NQ + i];
            sTau[i] = p[2 * NQ + 1 + i];
        }
        const float g = p[2 * NQ];
        float a = 0.0f, c = 0.0f;
#pragma unroll
        for (int i = NQ - 1; i >= 0; i--) {
            a += ms[i];
            c += ms[i] * ls[i] * ls[i] * (1.0f / 12.0f);
            ms_suf[i] = a;
            Is_suf[i] = c;
        }
#pragma unroll
        for (int i = 0; i < NQ; i++) {
            sGc[i] = g * ls[i] * (ms_suf[i] - 0.5f * ms[i]);
#pragma unroll
            for (int j = 0; j < NQ; j++) {
                if (i == j) {
                    sCo[i][j] = make_float2(
                        0.0f, ls[i] * ls[i] * (ms_suf[i] - 0.75f * ms[i]) + Is_suf[i]);
                } else {
                    const int mx = (i > j) ? i : j;
                    sCo[i][j] = make_float2(
                        ls[i] * ls[j] * (ms_suf[mx] - 0.5f * ms[mx]), Is_suf[mx]);
                }
            }
        }
    }
    __syncthreads();

    const int nHalf = Btot >> 1;                          // float2 outputs
    int t = blockIdx.x * blockDim.x + threadIdx.x;        // one thread per float2
    const bool valid = (t < nHalf);
    if (!valid) t = nHalf - 1;                            // samples never split (Btot%8==0)
    const int l = t & 3;                                  // lane within sample
    const int e0 = 2 * l, e1 = 2 * l + 1;                 // owned rows
    const int smp4 = (t >> 2) << 1;                       // sample's first float4 index

    // ---- redundant whole-sample loads (uniform per 4 lanes -> L1 broadcast) ----
    const float4 qA = ((const float4*)q_in)[smp4];
    const float4 qB = ((const float4*)q_in)[smp4 + 1];
    const float4 vA = ((const float4*)v_in)[smp4];
    const float4 vB = ((const float4*)v_in)[smp4 + 1];
    const float vf[NQ] = {vA.x, vA.y, vA.z, vA.w, vB.x, vB.y, vB.z, vB.w};

    // ---- full local cumsums + trig ----
    float sn[NQ], cn[NQ], cvf[NQ];
    {
        const float qf[NQ] = {qA.x, qA.y, qA.z, qA.w, qB.x, qB.y, qB.z, qB.w};
        float aq = 0.0f, av = 0.0f;
#pragma unroll
        for (int i = 0; i < NQ; i++) {
            aq += qf[i];
            av += vf[i];
            sn[i] = __sinf(aq);
            cn[i] = __cosf(aq);
            cvf[i] = av;
        }
    }

    // ---- select own-row values (2-level select trees; l runtime) ----
    const int hi = l >> 1, lo = l & 1;
    #define SEL4(arr, base) \
        (hi ? (lo ? arr[base + 6] : arr[base + 4]) : (lo ? arr[base + 2] : arr[base + 0]))
    const float sn0 = SEL4(sn, 0), sn1 = SEL4(sn, 1);
    const float cn0 = SEL4(cn, 0), cn1 = SEL4(cn, 1);
    const float cv0 = SEL4(cvf, 0), cv1 = SEL4(cvf, 1);
    const float v0  = SEL4(vf, 0),  v1  = SEL4(vf, 1);
    #undef SEL4

    // ---- build 2 owned matrix rows + Coriolis contractions (all local) ----
    float m[16];        // m[r*8+j] = M[e_r][j]
    float r1a = 0.f, r2a = 0.f, r1b = 0.f, r2b = 0.f;
#pragma unroll
    for (int j = 0; j < NQ; j++) {
        const float2 cA = sCo[e0][j];
        const float cdA = cn0 * cn[j] + sn0 * sn[j];
        const float sdA = sn0 * cn[j] - cn0 * sn[j];
        m[j] = cA.x * cdA + cA.y;
        const float TvA = cA.x * sdA * vf[j];
        r1a += TvA;
        r2a += TvA * cvf[j];

        const float2 cB = sCo[e1][j];
        const float cdB = cn1 * cn[j] + sn1 * sn[j];
        const float sdB = sn1 * cn[j] - cn1 * sn[j];
        m[8 + j] = cB.x * cdB + cB.y;
        const float TvB = cB.x * sdB * vf[j];
        r1b += TvB;
        r2b += TvB * cvf[j];
    }

    // ---- suffix sums across lanes (width-4 suffix scan, 2 shuffles each) ----
    const float prA = v0 * r1a;                    // own-row terms
    const float pgA = sGc[e0] * sn0;
    float sR = prA + v1 * r1b;
    float sG = pgA + sGc[e1] * sn1;
#pragma unroll
    for (int d = 1; d < 4; d <<= 1) {
        const float dR = __shfl_down_sync(FULLMASK, sR, d, 4);
        const float dG = __shfl_down_sync(FULLMASK, sG, d, 4);
        if (l + d < 4) { sR += dR; sG += dG; }
    }
    const float suffR0 = sR, suffR1 = sR - prA;
    const float suffG0 = sG, suffG1 = sG - pgA;

    // ---- rhs (u: own float2, coalesced) ----
    const float2 u2 = ((const float2*)u_in)[t];
    float x0 = sTau[e0] * u2.x - (-cv0 * r1a + r2a + suffR0) - suffG0;
    float x1 = sTau[e1] * u2.y - (-cv1 * r1b + r2b + suffR1) - suffG1;

    // ---- lane-parallel Gaussian elimination (SPD, no pivoting) ----
    float dinv0 = 0.f, dinv1 = 0.f;
#pragma unroll
    for (int k = 0; k < NQ; k++) {
        const int ok = k >> 1, ki = k & 1;  // owner lane / local row (compile-time)
        const float pivkk = __shfl_sync(FULLMASK, ki ? m[8 + k] : m[k], ok, 4);
        const float inv = __fdividef(1.0f, pivkk);
        if (l == ok) { if (ki) dinv1 = inv; else dinv0 = inv; }
        const float f0 = m[k] * inv;
        const float f1 = m[8 + k] * inv;
        const bool a0 = (e0 > k), a1 = (e1 > k);
#pragma unroll
        for (int j = k + 1; j < NQ; j++) {
            const float pj = __shfl_sync(FULLMASK, ki ? m[8 + j] : m[j], ok, 4);
            if (a0) m[j] -= f0 * pj;
            if (a1) m[8 + j] -= f1 * pj;
        }
        const float px = __shfl_sync(FULLMASK, ki ? x1 : x0, ok, 4);
        if (a0) x0 -= f0 * px;
        if (a1) x1 -= f1 * px;
    }

    // ---- back substitution (one broadcast per k) ----
#pragma unroll
    for (int k = NQ - 1; k >= 0; k--) {
        const int ok = k >> 1, ki = k & 1;
        const float sOwn = ki ? x1 * dinv1 : x0 * dinv0;
        const float s = __shfl_sync(FULLMASK, sOwn, ok, 4);
        if (l == ok) { if (ki) x1 = s; else x0 = s; }
        if (e0 < k) x0 -= m[k] * s;
        if (e1 < k) x1 -= m[8 + k] * s;
    }

    if (valid) ((float2*)out)[t] = make_float2(x0, x1);
}

extern "C" void kernel_launch(void* const* d_in, const int* in_sizes, int n_in,
                              void* d_out, int out_size) {
    const float* q = (const float*)d_in[0];
    const float* v = (const float*)d_in[1];
    const float* u = (const float*)d_in[2];
    const float* p = (const float*)d_in[3];
    float* out = (float*)d_out;
    const int Btot = in_sizes[0];       // B*NQ elements
    const int nThreads = Btot / 2;      // one thread per float2
    const int threads = 128;
    const int blocks = (nThreads + threads - 1) / threads;
    acrobot_dyn_kernel<<<blocks, threads>>>(q, v, u, p, out, Btot);
}

// round 15
// speedup vs baseline: 1.0536x; 1.0536x over previous
#include <cuda_runtime.h>
#include <cuda_bf16.h>

#define NQ 8
#define FULLMASK 0xffffffffu

// One sample per 4 lanes; lane l owns rows e0=2l, e1=2l+1.
// Every lane redundantly loads the whole sample's q,v (L1-broadcast) so all
// trig/cumsum work is local; shuffles remain only in GE pivot broadcasts.
__global__ void __launch_bounds__(128, 7) acrobot_dyn_kernel(
    const float* __restrict__ q_in, const float* __restrict__ v_in,
    const float* __restrict__ u_in, const float* __restrict__ p,
    float* __restrict__ out, int Btot /* = B*NQ */)
{
    // ---- uniform coefficient tables (once per CTA) ----
    __shared__ float2 sCo[NQ][NQ + 1];  // (A, IsOrD); diag = (0, D[i])
    __shared__ float sGc[NQ];           // g * ls_k * (ms_suf_k - 0.5*ms_k)
    __shared__ float sTau[NQ];

    if (threadIdx.x == 0) {
        float ms[NQ], ls[NQ], ms_suf[NQ], Is_suf[NQ];
#pragma unroll
        for (int i = 0; i < NQ; i++) {
            ms[i] = p[i];
            ls[i] = p[NQ + i];
            sTau[i] = p[2 * NQ + 1 + i];
        }
        const float g = p[2 * NQ];
        float a = 0.0f, c = 0.0f;
#pragma unroll
        for (int i = NQ - 1; i >= 0; i--) {
            a += ms[i];
            c += ms[i] * ls[i] * ls[i] * (1.0f / 12.0f);
            ms_suf[i] = a;
            Is_suf[i] = c;
        }
#pragma unroll
        for (int i = 0; i < NQ; i++) {
            sGc[i] = g * ls[i] * (ms_suf[i] - 0.5f * ms[i]);
#pragma unroll
            for (int j = 0; j < NQ; j++) {
                if (i == j) {
                    sCo[i][j] = make_float2(
                        0.0f, ls[i] * ls[i] * (ms_suf[i] - 0.75f * ms[i]) + Is_suf[i]);
                } else {
                    const int mx = (i > j) ? i : j;
                    sCo[i][j] = make_float2(
                        ls[i] * ls[j] * (ms_suf[mx] - 0.5f * ms[mx]), Is_suf[mx]);
                }
            }
        }
    }
    __syncthreads();

    const int nHalf = Btot >> 1;                          // float2 outputs
    int t = blockIdx.x * blockDim.x + threadIdx.x;        // one thread per float2
    const bool valid = (t < nHalf);
    if (!valid) t = nHalf - 1;                            // samples never split (Btot%8==0)
    const int l = t & 3;                                  // lane within sample
    const int e0 = 2 * l, e1 = 2 * l + 1;                 // owned rows
    const int smp4 = (t >> 2) << 1;                       // sample's first float4 index

    // ---- redundant whole-sample loads (uniform per 4 lanes -> L1 broadcast) ----
    const float4 qA = ((const float4*)q_in)[smp4];
    const float4 qB = ((const float4*)q_in)[smp4 + 1];
    const float4 vA = ((const float4*)v_in)[smp4];
    const float4 vB = ((const float4*)v_in)[smp4 + 1];
    const float vf[NQ] = {vA.x, vA.y, vA.z, vA.w, vB.x, vB.y, vB.z, vB.w};

    // ---- full local cumsums + trig ----
    float sn[NQ], cn[NQ], cvf[NQ];
    {
        const float qf[NQ] = {qA.x, qA.y, qA.z, qA.w, qB.x, qB.y, qB.z, qB.w};
        float aq = 0.0f, av = 0.0f;
#pragma unroll
        for (int i = 0; i < NQ; i++) {
            aq += qf[i];
            av += vf[i];
            sn[i] = __sinf(aq);
            cn[i] = __cosf(aq);
            cvf[i] = av;
        }
    }

    // ---- select own-row values (2-level select trees; l runtime) ----
    const int hi = l >> 1, lo = l & 1;
    #define SEL4(arr, base) \
        (hi ? (lo ? arr[base + 6] : arr[base + 4]) : (lo ? arr[base + 2] : arr[base + 0]))
    const float sn0 = SEL4(sn, 0), sn1 = SEL4(sn, 1);
    const float cn0 = SEL4(cn, 0), cn1 = SEL4(cn, 1);
    const float cv0 = SEL4(cvf, 0), cv1 = SEL4(cvf, 1);
    const float v0  = SEL4(vf, 0),  v1  = SEL4(vf, 1);
    #undef SEL4

    // ---- build 2 owned matrix rows + Coriolis contractions (all local) ----
    float m[16];        // m[r*8+j] = M[e_r][j]
    float r1a = 0.f, r2a = 0.f, r1b = 0.f, r2b = 0.f;
#pragma unroll
    for (int j = 0; j < NQ; j++) {
        const float2 cA = sCo[e0][j];
        const float cdA = cn0 * cn[j] + sn0 * sn[j];
        const float sdA = sn0 * cn[j] - cn0 * sn[j];
        m[j] = cA.x * cdA + cA.y;
        const float TvA = cA.x * sdA * vf[j];
        r1a += TvA;
        r2a += TvA * cvf[j];

        const float2 cB = sCo[e1][j];
        const float cdB = cn1 * cn[j] + sn1 * sn[j];
        const float sdB = sn1 * cn[j] - cn1 * sn[j];
        m[8 + j] = cB.x * cdB + cB.y;
        const float TvB = cB.x * sdB * vf[j];
        r1b += TvB;
        r2b += TvB * cvf[j];
    }

    // ---- suffix sums across lanes (width-4 suffix scan, 2 shuffles each) ----
    const float prA = v0 * r1a;                    // own-row terms
    const float pgA = sGc[e0] * sn0;
    float sR = prA + v1 * r1b;
    float sG = pgA + sGc[e1] * sn1;
#pragma unroll
    for (int d = 1; d < 4; d <<= 1) {
        const float dR = __shfl_down_sync(FULLMASK, sR, d, 4);
        const float dG = __shfl_down_sync(FULLMASK, sG, d, 4);
        if (l + d < 4) { sR += dR; sG += dG; }
    }
    const float suffR0 = sR, suffR1 = sR - prA;
    const float suffG0 = sG, suffG1 = sG - pgA;

    // ---- rhs (u: own float2, coalesced) ----
    const float2 u2 = ((const float2*)u_in)[t];
    float x0 = sTau[e0] * u2.x - (-cv0 * r1a + r2a + suffR0) - suffG0;
    float x1 = sTau[e1] * u2.y - (-cv1 * r1b + r2b + suffR1) - suffG1;

    // ---- lane-parallel Gaussian elimination (SPD, no pivoting) ----
    float dinv0 = 0.f, dinv1 = 0.f;
#pragma unroll
    for (int k = 0; k < NQ; k++) {
        const int ok = k >> 1, ki = k & 1;  // owner lane / local row (compile-time)
        const float pivkk = __shfl_sync(FULLMASK, ki ? m[8 + k] : m[k], ok, 4);
        const float inv = __fdividef(1.0f, pivkk);
        if (l == ok) { if (ki) dinv1 = inv; else dinv0 = inv; }
        const float f0 = m[k] * inv;
        const float f1 = m[8 + k] * inv;
        const bool a0 = (e0 > k), a1 = (e1 > k);
#pragma unroll
        for (int j = k + 1; j < NQ; j++) {
            const float pj = __shfl_sync(FULLMASK, ki ? m[8 + j] : m[j], ok, 4);
            if (a0) m[j] -= f0 * pj;
            if (a1) m[8 + j] -= f1 * pj;
        }
        const float px = __shfl_sync(FULLMASK, ki ? x1 : x0, ok, 4);
        if (a0) x0 -= f0 * px;
        if (a1) x1 -= f1 * px;
    }

    // ---- back substitution (one broadcast per k) ----
#pragma unroll
    for (int k = NQ - 1; k >= 0; k--) {
        const int ok = k >> 1, ki = k & 1;
        const float sOwn = ki ? x1 * dinv1 : x0 * dinv0;
        const float s = __shfl_sync(FULLMASK, sOwn, ok, 4);
        if (l == ok) { if (ki) x1 = s; else x0 = s; }
        if (e0 < k) x0 -= m[k] * s;
        if (e1 < k) x1 -= m[8 + k] * s;
    }

    if (valid) ((float2*)out)[t] = make_float2(x0, x1);
}

extern "C" void kernel_launch(void* const* d_in, const int* in_sizes, int n_in,
                              void* d_out, int out_size) {
    const float* q = (const float*)d_in[0];
    const float* v = (const float*)d_in[1];
    const float* u = (const float*)d_in[2];
    const float* p = (const float*)d_in[3];
    float* out = (float*)d_out;
    const int Btot = in_sizes[0];       // B*NQ elements
    const int nThreads = Btot / 2;      // one thread per float2
    const int threads = 128;
    const int blocks = (nThreads + threads - 1) / threads;
    acrobot_dyn_kernel<<<blocks, threads>>>(q, v, u, p, out, Btot);
}

// round 17
// speedup vs baseline: 1.2000x; 1.1389x over previous
#include <cuda_runtime.h>
#include <cuda_bf16.h>

#define NQ 8
#define FULLMASK 0xffffffffu

// One sample per 2 lanes; lane l owns matrix rows ebase = 4l .. 4l+3.
// Build phase fully local (redundant trig); solve uses batched, dependency-free
// pivot-row broadcasts: lane 0 finishes its block locally FIRST, then lane 1
// pulls final pivot rows in independent shuffle groups.
__global__ void __launch_bounds__(128, 6) acrobot_dyn_kernel(
    const float* __restrict__ q_in, const float* __restrict__ v_in,
    const float* __restrict__ u_in, const float* __restrict__ p,
    float* __restrict__ out, int Btot /* = B*NQ */)
{
    // ---- uniform coefficient tables (once per CTA) ----
    __shared__ float2 sCo[NQ][NQ + 1];  // (A, IsOrD); diag = (0, D[i])
    __shared__ float sGc[NQ];           // g * ls_k * (ms_suf_k - 0.5*ms_k)
    __shared__ float sTau[NQ];

    if (threadIdx.x == 0) {
        float ms[NQ], ls[NQ], ms_suf[NQ], Is_suf[NQ];
#pragma unroll
        for (int i = 0; i < NQ; i++) {
            ms[i] = p[i];
            ls[i] = p[NQ + i];
            sTau[i] = p[2 * NQ + 1 + i];
        }
        const float g = p[2 * NQ];
        float a = 0.0f, c = 0.0f;
#pragma unroll
        for (int i = NQ - 1; i >= 0; i--) {
            a += ms[i];
            c += ms[i] * ls[i] * ls[i] * (1.0f / 12.0f);
            ms_suf[i] = a;
            Is_suf[i] = c;
        }
#pragma unroll
        for (int i = 0; i < NQ; i++) {
            sGc[i] = g * ls[i] * (ms_suf[i] - 0.5f * ms[i]);
#pragma unroll
            for (int j = 0; j < NQ; j++) {
                if (i == j) {
                    sCo[i][j] = make_float2(
                        0.0f, ls[i] * ls[i] * (ms_suf[i] - 0.75f * ms[i]) + Is_suf[i]);
                } else {
                    const int mx = (i > j) ? i : j;
                    sCo[i][j] = make_float2(
                        ls[i] * ls[j] * (ms_suf[mx] - 0.5f * ms[mx]), Is_suf[mx]);
                }
            }
        }
    }
    __syncthreads();

    const int nQuads = Btot >> 2;
    int t4 = blockIdx.x * blockDim.x + threadIdx.x;
    const bool valid = (t4 < nQuads);
    if (!valid) t4 = nQuads - 1;
    const int l = threadIdx.x & 1;    // lane within sample
    const int ebase = l * 4;          // first owned row
    const int qlo = t4 & ~1;          // sample's low quad index

    // ---- load BOTH halves of the sample (partner hits the same L1 line) ----
    const float4 qA = ((const float4*)q_in)[qlo];
    const float4 qB = ((const float4*)q_in)[qlo + 1];
    const float4 vA = ((const float4*)v_in)[qlo];
    const float4 vB = ((const float4*)v_in)[qlo + 1];
    const float vf[NQ] = {vA.x, vA.y, vA.z, vA.w, vB.x, vB.y, vB.z, vB.w};

    // ---- full local cumsums + trig (zero shuffles) ----
    float sn[NQ], cn[NQ], w[NQ], cv_own[4];
    {
        const float qf[NQ] = {qA.x, qA.y, qA.z, qA.w, qB.x, qB.y, qB.z, qB.w};
        float aq = 0.0f, av = 0.0f;
        float cvf[NQ];
#pragma unroll
        for (int i = 0; i < NQ; i++) {
            aq += qf[i];
            av += vf[i];
            sn[i] = __sinf(aq);
            cn[i] = __cosf(aq);
            cvf[i] = av;
            w[i] = vf[i] * av;
        }
#pragma unroll
        for (int r = 0; r < 4; r++) cv_own[r] = l ? cvf[4 + r] : cvf[r];
    }

    // ---- build 4 owned matrix rows + Coriolis contractions (all local) ----
    float m[32];        // m[r*8+j] = M[ebase+r][j]
    float r1[4] = {0.f, 0.f, 0.f, 0.f}, r2[4] = {0.f, 0.f, 0.f, 0.f};
#pragma unroll
    for (int r = 0; r < 4; r++) {
        const float snr = l ? sn[4 + r] : sn[r];
        const float cnr = l ? cn[4 + r] : cn[r];
#pragma unroll
        for (int j = 0; j < NQ; j++) {
            const float2 c = sCo[ebase + r][j];
            const float cd = cnr * cn[j] + snr * sn[j];   // cos(cs_e - cs_j)
            const float sd = snr * cn[j] - cnr * sn[j];   // sin(cs_e - cs_j)
            m[r * 8 + j] = c.x * cd + c.y;                // diag: (A=0, D)
            const float T = c.x * sd;
            r1[r] += T * vf[j];
            r2[r] += T * w[j];
        }
    }

    // ---- gravity suffix: fully local; Coriolis suffix: one shuffle ----
    float suffG_own[4];
    {
        float sg[NQ];
        float acc = 0.0f;
#pragma unroll
        for (int i = NQ - 1; i >= 0; i--) {
            acc += sGc[i] * sn[i];
            sg[i] = acc;
        }
#pragma unroll
        for (int r = 0; r < 4; r++) suffG_own[r] = l ? sg[4 + r] : sg[r];
    }

    float suffR[4];
    {
        float pr = 0.0f;
#pragma unroll
        for (int r = 3; r >= 0; r--) {
            const float vr = l ? vf[4 + r] : vf[r];
            pr += vr * r1[r];
            suffR[r] = pr;
        }
        const float hi = __shfl_sync(FULLMASK, suffR[0], 1, 2);  // rows 4..7 total
        if (l == 0) {
#pragma unroll
            for (int r = 0; r < 4; r++) suffR[r] += hi;
        }
    }

    // ---- rhs ----
    const float4 u4 = ((const float4*)u_in)[t4];
    const float uu[4] = {u4.x, u4.y, u4.z, u4.w};
    float x[4];
#pragma unroll
    for (int r = 0; r < 4; r++) {
        const float Cv = -cv_own[r] * r1[r] + r2[r] + suffR[r];
        x[r] = sTau[ebase + r] * uu[r] - Cv - suffG_own[r];
    }

    // ================= solve M x = rhs (SPD, no pivoting) =================
    float dinv[4] = {0.f, 0.f, 0.f, 0.f};

    // Step 1: lane 0 eliminates pivots 0..3 among ITS OWN rows (fully local).
    // After this, lane 0's rows are the FINAL pivot rows for k=0..3.
    if (l == 0) {
#pragma unroll
        for (int k = 0; k < 4; k++) {
            const float inv = __fdividef(1.0f, m[k * 8 + k]);
            dinv[k] = inv;
#pragma unroll
            for (int r = k + 1; r < 4; r++) {
                const float f = m[r * 8 + k] * inv;
#pragma unroll
                for (int j = k + 1; j < NQ; j++) m[r * 8 + j] -= f * m[k * 8 + j];
                x[r] -= f * x[k];
            }
        }
    }

    // Steps 2+3: lane 1 pulls final pivot rows; the k-groups have NO cross-group
    // dependencies (lane 0 data is final), so shuffles pipeline freely.
#pragma unroll
    for (int k = 0; k < 4; k++) {
        const float pinv = __shfl_sync(FULLMASK, dinv[k], 0, 2);
        const float px   = __shfl_sync(FULLMASK, x[k], 0, 2);
        float pr[NQ];
#pragma unroll
        for (int j = k + 1; j < NQ; j++)
            pr[j] = __shfl_sync(FULLMASK, m[k * 8 + j], 0, 2);
        if (l == 1) {
#pragma unroll
            for (int r = 0; r < 4; r++) {
                const float f = m[r * 8 + k] * pinv;
#pragma unroll
                for (int j = k + 1; j < NQ; j++) m[r * 8 + j] -= f * pr[j];
                x[r] -= f * px;
            }
        }
    }

    // Step 4: lane 1 local elimination k=4..7 + local back-solve of x[4..7]
    if (l == 1) {
#pragma unroll
        for (int k = 4; k < NQ; k++) {
            const int ki = k - 4;
            const float inv = __fdividef(1.0f, m[ki * 8 + k]);
            dinv[ki] = inv;
#pragma unroll
            for (int r = ki + 1; r < 4; r++) {
                const float f = m[r * 8 + k] * inv;
#pragma unroll
                for (int j = k + 1; j < NQ; j++) m[r * 8 + j] -= f * m[ki * 8 + j];
                x[r] -= f * x[ki];
            }
        }
#pragma unroll
        for (int ki = 3; ki >= 0; ki--) {          // global row k = ki + 4
            float s = x[ki];
#pragma unroll
            for (int j = ki + 1; j < 4; j++) s -= m[ki * 8 + 4 + j] * x[j];
            x[ki] = s * dinv[ki];
        }
    }

    // Step 5: ship solved x[4..7] (4 independent shuffles); lane 0 finishes locally.
    float xs[4];
#pragma unroll
    for (int ki = 0; ki < 4; ki++)
        xs[ki] = __shfl_sync(FULLMASK, x[ki], 1, 2);
    if (l == 0) {
#pragma unroll
        for (int r = 0; r < 4; r++) {
            float s = x[r];
#pragma unroll
            for (int c = 0; c < 4; c++) s -= m[r * 8 + 4 + c] * xs[c];
            x[r] = s;
        }
#pragma unroll
        for (int r = 3; r >= 0; r--) {
            float s = x[r];
#pragma unroll
            for (int j = r + 1; j < 4; j++) s -= m[r * 8 + j] * x[j];
            x[r] = s * dinv[r];
        }
    }

    if (valid) ((float4*)out)[t4] = make_float4(x[0], x[1], x[2], x[3]);
}

extern "C" void kernel_launch(void* const* d_in, const int* in_sizes, int n_in,
                              void* d_out, int out_size) {
    const float* q = (const float*)d_in[0];
    const float* v = (const float*)d_in[1];
    const float* u = (const float*)d_in[2];
    const float* p = (const float*)d_in[3];
    float* out = (float*)d_out;
    const int Btot = in_sizes[0];       // B*NQ elements
    const int nThreads = Btot / 4;      // one thread per float4
    const int threads = 128;
    const int blocks = (nThreads + threads - 1) / threads;
    acrobot_dyn_kernel<<<blocks, threads>>>(q, v, u, p, out, Btot);
}